// round 1
// baseline (speedup 1.0000x reference)
#include <cuda_runtime.h>

#define BB   4
#define SS   2048
#define HH   1024
#define NHH  16
#define HDD  64
#define MM   (BB*SS)      // 8192
#define N3   (3*HH)       // 3072

// ---------------- scratch (__device__ globals; no runtime alloc) ----------------
__device__ float g_x[(size_t)MM * HH];                 // layernorm output
__device__ float g_q[(size_t)BB * NHH * SS * HDD];     // [b,h,s,d]
__device__ float g_k[(size_t)BB * NHH * SS * HDD];
__device__ float g_v[(size_t)BB * NHH * SS * HDD];
__device__ float g_ctx[(size_t)MM * HH];               // attention context [b,s,h*d]

// ---------------- layernorm ----------------
__global__ __launch_bounds__(256) void ln_kernel(const float* __restrict__ hs,
                                                 const float* __restrict__ gamma,
                                                 const float* __restrict__ beta) {
    const int row = blockIdx.x;
    const int tid = threadIdx.x;
    const float4 v = ((const float4*)(hs + (size_t)row * HH))[tid];
    float s  = v.x + v.y + v.z + v.w;
    float s2 = v.x*v.x + v.y*v.y + v.z*v.z + v.w*v.w;
    #pragma unroll
    for (int o = 16; o > 0; o >>= 1) {
        s  += __shfl_xor_sync(0xffffffffu, s,  o);
        s2 += __shfl_xor_sync(0xffffffffu, s2, o);
    }
    __shared__ float red[2][8];
    const int wid = tid >> 5, lane = tid & 31;
    if (lane == 0) { red[0][wid] = s; red[1][wid] = s2; }
    __syncthreads();
    float mean = 0.f, msq = 0.f;
    #pragma unroll
    for (int i = 0; i < 8; i++) { mean += red[0][i]; msq += red[1][i]; }
    mean *= (1.0f / HH);
    msq  *= (1.0f / HH);
    const float rstd = rsqrtf(msq - mean * mean + 1e-5f);
    const float4 g = ((const float4*)gamma)[tid];
    const float4 b = ((const float4*)beta)[tid];
    float4 o;
    o.x = (v.x - mean) * rstd * g.x + b.x;
    o.y = (v.y - mean) * rstd * g.y + b.y;
    o.z = (v.z - mean) * rstd * g.z + b.z;
    o.w = (v.w - mean) * rstd * g.w + b.w;
    ((float4*)(g_x + (size_t)row * HH))[tid] = o;
}

// ---------------- QKV GEMM: g_x[8192,1024] @ W[1024,3072] + b -> q/k/v scatter ----
__global__ __launch_bounds__(256) void qkv_gemm_kernel(const float* __restrict__ W,
                                                       const float* __restrict__ bias) {
    __shared__ float As[16][132];   // [k][m], padded
    __shared__ float Bs[16][128];   // [k][n]
    const int tid = threadIdx.x;
    const int ty = tid >> 4, tx = tid & 15;
    const int bm = blockIdx.y, bn = blockIdx.x;
    const float* A  = g_x + (size_t)bm * 128 * HH;
    const float* Bw = W + bn * 128;

    float acc[8][8];
    #pragma unroll
    for (int i = 0; i < 8; i++)
        #pragma unroll
        for (int j = 0; j < 8; j++) acc[i][j] = 0.f;

    const int ar = tid >> 1, akb = (tid & 1) * 8;
    const int br = tid >> 5, bc = (tid & 31) * 4;

    float4 a0 = *(const float4*)(A + (size_t)ar * HH + akb);
    float4 a1 = *(const float4*)(A + (size_t)ar * HH + akb + 4);
    float4 b0 = *(const float4*)(Bw + (size_t)br * N3 + bc);
    float4 b1 = *(const float4*)(Bw + (size_t)(br + 8) * N3 + bc);

    for (int kt = 0; kt < 64; kt++) {
        __syncthreads();
        As[akb+0][ar] = a0.x; As[akb+1][ar] = a0.y; As[akb+2][ar] = a0.z; As[akb+3][ar] = a0.w;
        As[akb+4][ar] = a1.x; As[akb+5][ar] = a1.y; As[akb+6][ar] = a1.z; As[akb+7][ar] = a1.w;
        *(float4*)&Bs[br][bc]     = b0;
        *(float4*)&Bs[br + 8][bc] = b1;
        __syncthreads();
        if (kt < 63) {
            const int k0 = (kt + 1) * 16;
            a0 = *(const float4*)(A + (size_t)ar * HH + k0 + akb);
            a1 = *(const float4*)(A + (size_t)ar * HH + k0 + akb + 4);
            b0 = *(const float4*)(Bw + (size_t)(k0 + br) * N3 + bc);
            b1 = *(const float4*)(Bw + (size_t)(k0 + br + 8) * N3 + bc);
        }
        #pragma unroll
        for (int kk = 0; kk < 16; kk++) {
            const float4 af0 = *(const float4*)&As[kk][ty * 8];
            const float4 af1 = *(const float4*)&As[kk][ty * 8 + 4];
            const float4 bf0 = *(const float4*)&Bs[kk][tx * 8];
            const float4 bf1 = *(const float4*)&Bs[kk][tx * 8 + 4];
            const float a[8] = {af0.x, af0.y, af0.z, af0.w, af1.x, af1.y, af1.z, af1.w};
            const float b[8] = {bf0.x, bf0.y, bf0.z, bf0.w, bf1.x, bf1.y, bf1.z, bf1.w};
            #pragma unroll
            for (int i = 0; i < 8; i++)
                #pragma unroll
                for (int j = 0; j < 8; j++) acc[i][j] += a[i] * b[j];
        }
    }
    // scatter epilogue into [b,h,s,d]
    #pragma unroll
    for (int i = 0; i < 8; i++) {
        const int m = bm * 128 + ty * 8 + i;
        const int bidx = m >> 11, srow = m & 2047;
        #pragma unroll
        for (int jj = 0; jj < 8; jj += 4) {
            const int n = bn * 128 + tx * 8 + jj;
            const float4 b4 = *(const float4*)(bias + n);
            float4 c = make_float4(acc[i][jj] + b4.x, acc[i][jj+1] + b4.y,
                                   acc[i][jj+2] + b4.z, acc[i][jj+3] + b4.w);
            const int part = n >> 10;
            const int r = n & 1023;
            const int hh = r >> 6, d = r & 63;
            float* dst = (part == 0) ? g_q : ((part == 1) ? g_k : g_v);
            *(float4*)(dst + ((size_t)((bidx * NHH + hh) * SS + srow)) * HDD + d) = c;
        }
    }
}

// ---------------- flash attention + raw score emission ----------------
// block = (b, h, q-tile of 64 rows). 256 threads: ty=tid/16 (q), tx=tid%16 (k or d), 4x4 microtile.
#define ATTN_SMEM (3 * 64 * 68 * 4)
__global__ __launch_bounds__(256) void attn_kernel(const float* __restrict__ amask,
                                                   float* __restrict__ scores_out) {
    extern __shared__ float sm[];
    float (*Qst)[68] = (float (*)[68])sm;              // [d][q]
    float (*KPs)[68] = (float (*)[68])(sm + 64 * 68);  // K as [d][kc], then P as [kc][q]
    float (*Vs )[68] = (float (*)[68])(sm + 2 * 64 * 68); // [kc][d]

    const int qt = 31 - blockIdx.x;   // heavy tiles first
    const int h  = blockIdx.y;
    const int b  = blockIdx.z;
    const int tid = threadIdx.x;
    const int ty = tid >> 4, tx = tid & 15;
    const int q0 = qt * 64;

    const float* Qg = g_q + (size_t)(b * NHH + h) * SS * HDD;
    const float* Kg = g_k + (size_t)(b * NHH + h) * SS * HDD;
    const float* Vg = g_v + (size_t)(b * NHH + h) * SS * HDD;
    float* sc = scores_out ? scores_out + ((size_t)(b * NHH + h) * SS + q0) * SS : nullptr;
    const float* am_base = amask + b * SS;

    // load Q transposed
    {
        const int r = tid >> 2;
        const int dbase = (tid & 3) * 16;
        const float4* src = (const float4*)(Qg + (size_t)(q0 + r) * HDD + dbase);
        #pragma unroll
        for (int i = 0; i < 4; i++) {
            const float4 v = src[i];
            Qst[dbase + 4*i + 0][r] = v.x; Qst[dbase + 4*i + 1][r] = v.y;
            Qst[dbase + 4*i + 2][r] = v.z; Qst[dbase + 4*i + 3][r] = v.w;
        }
    }

    float acc[4][4];
    float mrow[4], lrow[4];
    #pragma unroll
    for (int i = 0; i < 4; i++) {
        mrow[i] = -1e30f; lrow[i] = 0.f;
        #pragma unroll
        for (int j = 0; j < 4; j++) acc[i][j] = 0.f;
    }

    for (int kt = 0; kt <= qt; kt++) {
        const int k0 = kt * 64;
        __syncthreads();   // prior iteration done reading KPs/Vs
        {
            const int r = tid >> 2;
            const int dbase = (tid & 3) * 16;
            const float4* ks = (const float4*)(Kg + (size_t)(k0 + r) * HDD + dbase);
            const float4* vs = (const float4*)(Vg + (size_t)(k0 + r) * HDD + dbase);
            #pragma unroll
            for (int i = 0; i < 4; i++) {
                const float4 kv = ks[i];
                KPs[dbase + 4*i + 0][r] = kv.x; KPs[dbase + 4*i + 1][r] = kv.y;
                KPs[dbase + 4*i + 2][r] = kv.z; KPs[dbase + 4*i + 3][r] = kv.w;
                *(float4*)&Vs[r][dbase + 4*i] = vs[i];
            }
        }
        __syncthreads();

        float s[4][4];
        #pragma unroll
        for (int i = 0; i < 4; i++)
            #pragma unroll
            for (int j = 0; j < 4; j++) s[i][j] = 0.f;
        #pragma unroll
        for (int kk = 0; kk < 64; kk++) {
            const float4 qf = *(const float4*)&Qst[kk][ty * 4];
            const float4 kf = *(const float4*)&KPs[kk][tx * 4];
            const float qa[4] = {qf.x, qf.y, qf.z, qf.w};
            const float ka[4] = {kf.x, kf.y, kf.z, kf.w};
            #pragma unroll
            for (int i = 0; i < 4; i++)
                #pragma unroll
                for (int j = 0; j < 4; j++) s[i][j] += qa[i] * ka[j];
        }

        const float4 am4 = *(const float4*)(am_base + k0 + tx * 4);
        const float am[4] = {am4.x, am4.y, am4.z, am4.w};
        const bool diag = (kt == qt);
        #pragma unroll
        for (int i = 0; i < 4; i++) {
            const int qg = q0 + ty * 4 + i;
            #pragma unroll
            for (int j = 0; j < 4; j++) {
                float v = s[i][j] * 0.125f;
                if (diag && (k0 + tx * 4 + j) > qg) v = -10000.0f;
                v += am[j] * -10000.0f;
                s[i][j] = v;
            }
        }
        if (sc) {
            #pragma unroll
            for (int i = 0; i < 4; i++)
                *(float4*)&sc[(size_t)(ty * 4 + i) * SS + k0 + tx * 4] =
                    make_float4(s[i][0], s[i][1], s[i][2], s[i][3]);
        }

        // online softmax
        #pragma unroll
        for (int i = 0; i < 4; i++) {
            float tmax = fmaxf(fmaxf(s[i][0], s[i][1]), fmaxf(s[i][2], s[i][3]));
            #pragma unroll
            for (int o = 8; o > 0; o >>= 1)
                tmax = fmaxf(tmax, __shfl_xor_sync(0xffffffffu, tmax, o, 16));
            const float mnew = fmaxf(mrow[i], tmax);
            const float alpha = __expf(mrow[i] - mnew);
            float psum = 0.f;
            #pragma unroll
            for (int j = 0; j < 4; j++) { s[i][j] = __expf(s[i][j] - mnew); psum += s[i][j]; }
            #pragma unroll
            for (int o = 8; o > 0; o >>= 1)
                psum += __shfl_xor_sync(0xffffffffu, psum, o, 16);
            lrow[i] = lrow[i] * alpha + psum;
            mrow[i] = mnew;
            #pragma unroll
            for (int j = 0; j < 4; j++) acc[i][j] *= alpha;
        }

        __syncthreads();   // everyone done reading K from KPs
        #pragma unroll
        for (int i = 0; i < 4; i++)
            #pragma unroll
            for (int j = 0; j < 4; j++) KPs[tx * 4 + j][ty * 4 + i] = s[i][j];  // P^T
        __syncthreads();

        #pragma unroll
        for (int kk = 0; kk < 64; kk++) {
            const float4 pf = *(const float4*)&KPs[kk][ty * 4];
            const float4 vf = *(const float4*)&Vs[kk][tx * 4];
            const float pa[4] = {pf.x, pf.y, pf.z, pf.w};
            const float va[4] = {vf.x, vf.y, vf.z, vf.w};
            #pragma unroll
            for (int i = 0; i < 4; i++)
                #pragma unroll
                for (int j = 0; j < 4; j++) acc[i][j] += pa[i] * va[j];
        }
    }

    // fully causal-masked tail tiles: write -10000 (+ attn_mask term)
    if (sc) {
        for (int kt = qt + 1; kt < 32; kt++) {
            const int k0 = kt * 64;
            const float4 am4 = *(const float4*)(am_base + k0 + tx * 4);
            float4 val;
            val.x = -10000.0f + am4.x * -10000.0f;
            val.y = -10000.0f + am4.y * -10000.0f;
            val.z = -10000.0f + am4.z * -10000.0f;
            val.w = -10000.0f + am4.w * -10000.0f;
            #pragma unroll
            for (int i = 0; i < 4; i++)
                *(float4*)&sc[(size_t)(ty * 4 + i) * SS + k0 + tx * 4] = val;
        }
    }

    // ctx = acc / l  -> g_ctx[b,s,h*64+d]
    #pragma unroll
    for (int i = 0; i < 4; i++) {
        const float inv = 1.0f / lrow[i];
        const float4 o = make_float4(acc[i][0] * inv, acc[i][1] * inv,
                                     acc[i][2] * inv, acc[i][3] * inv);
        *(float4*)(g_ctx + ((size_t)(b * SS) + q0 + ty * 4 + i) * HH + h * HDD + tx * 4) = o;
    }
}

// ---------------- projection GEMM + residual ----------------
__global__ __launch_bounds__(256) void proj_gemm_kernel(const float* __restrict__ W,
                                                        const float* __restrict__ bias,
                                                        const float* __restrict__ hs,
                                                        float* __restrict__ out) {
    __shared__ float As[16][132];
    __shared__ float Bs[16][128];
    const int tid = threadIdx.x;
    const int ty = tid >> 4, tx = tid & 15;
    const int bm = blockIdx.y, bn = blockIdx.x;
    const float* A  = g_ctx + (size_t)bm * 128 * HH;
    const float* Bw = W + bn * 128;

    float acc[8][8];
    #pragma unroll
    for (int i = 0; i < 8; i++)
        #pragma unroll
        for (int j = 0; j < 8; j++) acc[i][j] = 0.f;

    const int ar = tid >> 1, akb = (tid & 1) * 8;
    const int br = tid >> 5, bc = (tid & 31) * 4;

    float4 a0 = *(const float4*)(A + (size_t)ar * HH + akb);
    float4 a1 = *(const float4*)(A + (size_t)ar * HH + akb + 4);
    float4 b0 = *(const float4*)(Bw + (size_t)br * HH + bc);
    float4 b1 = *(const float4*)(Bw + (size_t)(br + 8) * HH + bc);

    for (int kt = 0; kt < 64; kt++) {
        __syncthreads();
        As[akb+0][ar] = a0.x; As[akb+1][ar] = a0.y; As[akb+2][ar] = a0.z; As[akb+3][ar] = a0.w;
        As[akb+4][ar] = a1.x; As[akb+5][ar] = a1.y; As[akb+6][ar] = a1.z; As[akb+7][ar] = a1.w;
        *(float4*)&Bs[br][bc]     = b0;
        *(float4*)&Bs[br + 8][bc] = b1;
        __syncthreads();
        if (kt < 63) {
            const int k0 = (kt + 1) * 16;
            a0 = *(const float4*)(A + (size_t)ar * HH + k0 + akb);
            a1 = *(const float4*)(A + (size_t)ar * HH + k0 + akb + 4);
            b0 = *(const float4*)(Bw + (size_t)(k0 + br) * HH + bc);
            b1 = *(const float4*)(Bw + (size_t)(k0 + br + 8) * HH + bc);
        }
        #pragma unroll
        for (int kk = 0; kk < 16; kk++) {
            const float4 af0 = *(const float4*)&As[kk][ty * 8];
            const float4 af1 = *(const float4*)&As[kk][ty * 8 + 4];
            const float4 bf0 = *(const float4*)&Bs[kk][tx * 8];
            const float4 bf1 = *(const float4*)&Bs[kk][tx * 8 + 4];
            const float a[8] = {af0.x, af0.y, af0.z, af0.w, af1.x, af1.y, af1.z, af1.w};
            const float b[8] = {bf0.x, bf0.y, bf0.z, bf0.w, bf1.x, bf1.y, bf1.z, bf1.w};
            #pragma unroll
            for (int i = 0; i < 8; i++)
                #pragma unroll
                for (int j = 0; j < 8; j++) acc[i][j] += a[i] * b[j];
        }
    }
    #pragma unroll
    for (int i = 0; i < 8; i++) {
        const int m = bm * 128 + ty * 8 + i;
        #pragma unroll
        for (int jj = 0; jj < 8; jj += 4) {
            const int n = bn * 128 + tx * 8 + jj;
            const float4 b4 = *(const float4*)(bias + n);
            const float4 r4 = *(const float4*)(hs + (size_t)m * HH + n);
            float4 c = make_float4(acc[i][jj]   + b4.x + r4.x,
                                   acc[i][jj+1] + b4.y + r4.y,
                                   acc[i][jj+2] + b4.z + r4.z,
                                   acc[i][jj+3] + b4.w + r4.w);
            *(float4*)(out + (size_t)m * HH + n) = c;
        }
    }
}

// ---------------- launch ----------------
extern "C" void kernel_launch(void* const* d_in, const int* in_sizes, int n_in,
                              void* d_out, int out_size) {
    const float* hs       = (const float*)d_in[0];
    const float* amask    = (const float*)d_in[1];
    const float* c_attn_w = (const float*)d_in[2];
    const float* c_attn_b = (const float*)d_in[3];
    const float* c_proj_w = (const float*)d_in[4];
    const float* c_proj_b = (const float*)d_in[5];
    const float* ln_g     = (const float*)d_in[6];
    const float* ln_b     = (const float*)d_in[7];
    float* out = (float*)d_out;
    float* scores = (out_size > MM * HH) ? (out + (size_t)MM * HH) : nullptr;

    ln_kernel<<<MM, 256>>>(hs, ln_g, ln_b);
    qkv_gemm_kernel<<<dim3(N3 / 128, MM / 128), 256>>>(c_attn_w, c_attn_b);
    cudaFuncSetAttribute(attn_kernel, cudaFuncAttributeMaxDynamicSharedMemorySize, ATTN_SMEM);
    attn_kernel<<<dim3(32, NHH, BB), 256, ATTN_SMEM>>>(amask, scores);
    proj_gemm_kernel<<<dim3(HH / 128, MM / 128), 256>>>(c_proj_w, c_proj_b, hs, out);
}

// round 2
// speedup vs baseline: 1.0468x; 1.0468x over previous
#include <cuda_runtime.h>

#define BB   4
#define SS   2048
#define HH   1024
#define NHH  16
#define HDD  64
#define MM   (BB*SS)      // 8192
#define N3   (3*HH)       // 3072

typedef unsigned long long ull;

// ---------------- packed f32x2 helpers (Blackwell FFMA2 — PTX-only) ----------------
__device__ __forceinline__ ull ffma2(ull a, ull b, ull c) {
    ull d;
    asm("fma.rn.f32x2 %0, %1, %2, %3;" : "=l"(d) : "l"(a), "l"(b), "l"(c));
    return d;
}
__device__ __forceinline__ ull fmul2(ull a, ull b) {
    ull d;
    asm("mul.rn.f32x2 %0, %1, %2;" : "=l"(d) : "l"(a), "l"(b));
    return d;
}
__device__ __forceinline__ ull pack2(float x) {
    ull r;
    asm("mov.b64 %0, {%1, %1};" : "=l"(r) : "f"(x));
    return r;
}
__device__ __forceinline__ float2 unpack2(ull v) {
    float2 r;
    asm("mov.b64 {%0, %1}, %2;" : "=f"(r.x), "=f"(r.y) : "l"(v));
    return r;
}

// ---------------- scratch (__device__ globals; no runtime alloc) ----------------
__device__ float g_x[(size_t)MM * HH];                 // layernorm output
__device__ float g_q[(size_t)BB * NHH * SS * HDD];     // [b,h,s,d]
__device__ float g_k[(size_t)BB * NHH * SS * HDD];
__device__ float g_v[(size_t)BB * NHH * SS * HDD];
__device__ float g_ctx[(size_t)MM * HH];               // attention context [b,s,h*d]

// ---------------- layernorm ----------------
__global__ __launch_bounds__(256) void ln_kernel(const float* __restrict__ hs,
                                                 const float* __restrict__ gamma,
                                                 const float* __restrict__ beta) {
    const int row = blockIdx.x;
    const int tid = threadIdx.x;
    const float4 v = ((const float4*)(hs + (size_t)row * HH))[tid];
    float s  = v.x + v.y + v.z + v.w;
    float s2 = v.x*v.x + v.y*v.y + v.z*v.z + v.w*v.w;
    #pragma unroll
    for (int o = 16; o > 0; o >>= 1) {
        s  += __shfl_xor_sync(0xffffffffu, s,  o);
        s2 += __shfl_xor_sync(0xffffffffu, s2, o);
    }
    __shared__ float red[2][8];
    const int wid = tid >> 5, lane = tid & 31;
    if (lane == 0) { red[0][wid] = s; red[1][wid] = s2; }
    __syncthreads();
    float mean = 0.f, msq = 0.f;
    #pragma unroll
    for (int i = 0; i < 8; i++) { mean += red[0][i]; msq += red[1][i]; }
    mean *= (1.0f / HH);
    msq  *= (1.0f / HH);
    const float rstd = rsqrtf(msq - mean * mean + 1e-5f);
    const float4 g = ((const float4*)gamma)[tid];
    const float4 b = ((const float4*)beta)[tid];
    float4 o;
    o.x = (v.x - mean) * rstd * g.x + b.x;
    o.y = (v.y - mean) * rstd * g.y + b.y;
    o.z = (v.z - mean) * rstd * g.z + b.z;
    o.w = (v.w - mean) * rstd * g.w + b.w;
    ((float4*)(g_x + (size_t)row * HH))[tid] = o;
}

// ---------------- QKV GEMM: g_x[8192,1024] @ W[1024,3072] + b -> q/k/v scatter ----
__global__ __launch_bounds__(256) void qkv_gemm_kernel(const float* __restrict__ W,
                                                       const float* __restrict__ bias) {
    __shared__ float As[16][132];   // [k][m], padded
    __shared__ float Bs[16][128];   // [k][n]
    const int tid = threadIdx.x;
    const int ty = tid >> 4, tx = tid & 15;
    const int bm = blockIdx.y, bn = blockIdx.x;
    const float* A  = g_x + (size_t)bm * 128 * HH;
    const float* Bw = W + bn * 128;

    ull acc2[8][4];
    #pragma unroll
    for (int i = 0; i < 8; i++)
        #pragma unroll
        for (int j = 0; j < 4; j++) acc2[i][j] = 0ull;

    const int ar = tid >> 1, akb = (tid & 1) * 8;
    const int br = tid >> 5, bc = (tid & 31) * 4;

    float4 a0 = *(const float4*)(A + (size_t)ar * HH + akb);
    float4 a1 = *(const float4*)(A + (size_t)ar * HH + akb + 4);
    float4 b0 = *(const float4*)(Bw + (size_t)br * N3 + bc);
    float4 b1 = *(const float4*)(Bw + (size_t)(br + 8) * N3 + bc);

    for (int kt = 0; kt < 64; kt++) {
        __syncthreads();
        As[akb+0][ar] = a0.x; As[akb+1][ar] = a0.y; As[akb+2][ar] = a0.z; As[akb+3][ar] = a0.w;
        As[akb+4][ar] = a1.x; As[akb+5][ar] = a1.y; As[akb+6][ar] = a1.z; As[akb+7][ar] = a1.w;
        *(float4*)&Bs[br][bc]     = b0;
        *(float4*)&Bs[br + 8][bc] = b1;
        __syncthreads();
        if (kt < 63) {
            const int k0 = (kt + 1) * 16;
            a0 = *(const float4*)(A + (size_t)ar * HH + k0 + akb);
            a1 = *(const float4*)(A + (size_t)ar * HH + k0 + akb + 4);
            b0 = *(const float4*)(Bw + (size_t)(k0 + br) * N3 + bc);
            b1 = *(const float4*)(Bw + (size_t)(k0 + br + 8) * N3 + bc);
        }
        #pragma unroll
        for (int kk = 0; kk < 16; kk++) {
            const float4 af0 = *(const float4*)&As[kk][ty * 8];
            const float4 af1 = *(const float4*)&As[kk][ty * 8 + 4];
            const ull* bp = (const ull*)&Bs[kk][tx * 8];
            const ull bb0 = bp[0], bb1 = bp[1], bb2 = bp[2], bb3 = bp[3];
            const float a[8] = {af0.x, af0.y, af0.z, af0.w, af1.x, af1.y, af1.z, af1.w};
            #pragma unroll
            for (int i = 0; i < 8; i++) {
                const ull ai = pack2(a[i]);
                acc2[i][0] = ffma2(ai, bb0, acc2[i][0]);
                acc2[i][1] = ffma2(ai, bb1, acc2[i][1]);
                acc2[i][2] = ffma2(ai, bb2, acc2[i][2]);
                acc2[i][3] = ffma2(ai, bb3, acc2[i][3]);
            }
        }
    }
    // scatter epilogue into [b,h,s,d]
    #pragma unroll
    for (int i = 0; i < 8; i++) {
        const int m = bm * 128 + ty * 8 + i;
        const int bidx = m >> 11, srow = m & 2047;
        #pragma unroll
        for (int jj = 0; jj < 2; jj++) {
            const int n = bn * 128 + tx * 8 + jj * 4;
            const float4 b4 = *(const float4*)(bias + n);
            const float2 v0 = unpack2(acc2[i][jj * 2]);
            const float2 v1 = unpack2(acc2[i][jj * 2 + 1]);
            float4 c = make_float4(v0.x + b4.x, v0.y + b4.y, v1.x + b4.z, v1.y + b4.w);
            const int part = n >> 10;
            const int r = n & 1023;
            const int hh = r >> 6, d = r & 63;
            float* dst = (part == 0) ? g_q : ((part == 1) ? g_k : g_v);
            *(float4*)(dst + ((size_t)((bidx * NHH + hh) * SS + srow)) * HDD + d) = c;
        }
    }
}

// ---------------- flash attention + raw score emission ----------------
// block = (b, h, q-tile of 64 rows). 256 threads: ty=tid/16 (q), tx=tid%16 (k or d), 4x4 microtile.
#define ATTN_SMEM (3 * 64 * 68 * 4)
__global__ __launch_bounds__(256) void attn_kernel(const float* __restrict__ amask,
                                                   float* __restrict__ scores_out) {
    extern __shared__ float sm[];
    float (*Qst)[68] = (float (*)[68])sm;              // [d][q]
    float (*KPs)[68] = (float (*)[68])(sm + 64 * 68);  // K as [d][kc], then P as [kc][q]
    float (*Vs )[68] = (float (*)[68])(sm + 2 * 64 * 68); // [kc][d]

    const int qt = 31 - blockIdx.x;   // heavy tiles first
    const int h  = blockIdx.y;
    const int b  = blockIdx.z;
    const int tid = threadIdx.x;
    const int ty = tid >> 4, tx = tid & 15;
    const int q0 = qt * 64;

    const float* Qg = g_q + (size_t)(b * NHH + h) * SS * HDD;
    const float* Kg = g_k + (size_t)(b * NHH + h) * SS * HDD;
    const float* Vg = g_v + (size_t)(b * NHH + h) * SS * HDD;
    float* sc = scores_out ? scores_out + ((size_t)(b * NHH + h) * SS + q0) * SS : nullptr;
    const float* am_base = amask + b * SS;

    // load Q transposed
    {
        const int r = tid >> 2;
        const int dbase = (tid & 3) * 16;
        const float4* src = (const float4*)(Qg + (size_t)(q0 + r) * HDD + dbase);
        #pragma unroll
        for (int i = 0; i < 4; i++) {
            const float4 v = src[i];
            Qst[dbase + 4*i + 0][r] = v.x; Qst[dbase + 4*i + 1][r] = v.y;
            Qst[dbase + 4*i + 2][r] = v.z; Qst[dbase + 4*i + 3][r] = v.w;
        }
    }

    ull acc2[4][2];
    float mrow[4], lrow[4];
    #pragma unroll
    for (int i = 0; i < 4; i++) {
        mrow[i] = -1e30f; lrow[i] = 0.f;
        acc2[i][0] = 0ull; acc2[i][1] = 0ull;
    }

    for (int kt = 0; kt <= qt; kt++) {
        const int k0 = kt * 64;
        __syncthreads();   // prior iteration done reading KPs/Vs
        {
            const int r = tid >> 2;
            const int dbase = (tid & 3) * 16;
            const float4* ks = (const float4*)(Kg + (size_t)(k0 + r) * HDD + dbase);
            const float4* vs = (const float4*)(Vg + (size_t)(k0 + r) * HDD + dbase);
            #pragma unroll
            for (int i = 0; i < 4; i++) {
                const float4 kv = ks[i];
                KPs[dbase + 4*i + 0][r] = kv.x; KPs[dbase + 4*i + 1][r] = kv.y;
                KPs[dbase + 4*i + 2][r] = kv.z; KPs[dbase + 4*i + 3][r] = kv.w;
                *(float4*)&Vs[r][dbase + 4*i] = vs[i];
            }
        }
        __syncthreads();

        ull s2[4][2];
        #pragma unroll
        for (int i = 0; i < 4; i++) { s2[i][0] = 0ull; s2[i][1] = 0ull; }
        #pragma unroll
        for (int kk = 0; kk < 64; kk++) {
            const float4 qf = *(const float4*)&Qst[kk][ty * 4];
            const ull* kp = (const ull*)&KPs[kk][tx * 4];
            const ull kk0 = kp[0], kk1 = kp[1];
            const float qa[4] = {qf.x, qf.y, qf.z, qf.w};
            #pragma unroll
            for (int i = 0; i < 4; i++) {
                const ull qi = pack2(qa[i]);
                s2[i][0] = ffma2(qi, kk0, s2[i][0]);
                s2[i][1] = ffma2(qi, kk1, s2[i][1]);
            }
        }

        float s[4][4];
        #pragma unroll
        for (int i = 0; i < 4; i++) {
            const float2 v0 = unpack2(s2[i][0]);
            const float2 v1 = unpack2(s2[i][1]);
            s[i][0] = v0.x; s[i][1] = v0.y; s[i][2] = v1.x; s[i][3] = v1.y;
        }

        const float4 am4 = *(const float4*)(am_base + k0 + tx * 4);
        const float am[4] = {am4.x, am4.y, am4.z, am4.w};
        const bool diag = (kt == qt);
        #pragma unroll
        for (int i = 0; i < 4; i++) {
            const int qg = q0 + ty * 4 + i;
            #pragma unroll
            for (int j = 0; j < 4; j++) {
                float v = s[i][j] * 0.125f;
                if (diag && (k0 + tx * 4 + j) > qg) v = -10000.0f;
                v += am[j] * -10000.0f;
                s[i][j] = v;
            }
        }
        if (sc) {
            #pragma unroll
            for (int i = 0; i < 4; i++)
                *(float4*)&sc[(size_t)(ty * 4 + i) * SS + k0 + tx * 4] =
                    make_float4(s[i][0], s[i][1], s[i][2], s[i][3]);
        }

        // online softmax
        #pragma unroll
        for (int i = 0; i < 4; i++) {
            float tmax = fmaxf(fmaxf(s[i][0], s[i][1]), fmaxf(s[i][2], s[i][3]));
            #pragma unroll
            for (int o = 8; o > 0; o >>= 1)
                tmax = fmaxf(tmax, __shfl_xor_sync(0xffffffffu, tmax, o, 16));
            const float mnew = fmaxf(mrow[i], tmax);
            const float alpha = __expf(mrow[i] - mnew);
            float psum = 0.f;
            #pragma unroll
            for (int j = 0; j < 4; j++) { s[i][j] = __expf(s[i][j] - mnew); psum += s[i][j]; }
            #pragma unroll
            for (int o = 8; o > 0; o >>= 1)
                psum += __shfl_xor_sync(0xffffffffu, psum, o, 16);
            lrow[i] = lrow[i] * alpha + psum;
            mrow[i] = mnew;
            const ull al2 = pack2(alpha);
            acc2[i][0] = fmul2(acc2[i][0], al2);
            acc2[i][1] = fmul2(acc2[i][1], al2);
        }

        __syncthreads();   // everyone done reading K from KPs
        #pragma unroll
        for (int i = 0; i < 4; i++)
            #pragma unroll
            for (int j = 0; j < 4; j++) KPs[tx * 4 + j][ty * 4 + i] = s[i][j];  // P^T
        __syncthreads();

        #pragma unroll
        for (int kk = 0; kk < 64; kk++) {
            const float4 pf = *(const float4*)&KPs[kk][ty * 4];
            const ull* vp = (const ull*)&Vs[kk][tx * 4];
            const ull vv0 = vp[0], vv1 = vp[1];
            const float pa[4] = {pf.x, pf.y, pf.z, pf.w};
            #pragma unroll
            for (int i = 0; i < 4; i++) {
                const ull pi = pack2(pa[i]);
                acc2[i][0] = ffma2(pi, vv0, acc2[i][0]);
                acc2[i][1] = ffma2(pi, vv1, acc2[i][1]);
            }
        }
    }

    // fully causal-masked tail tiles: write -10000 (+ attn_mask term)
    if (sc) {
        for (int kt = qt + 1; kt < 32; kt++) {
            const int k0 = kt * 64;
            const float4 am4 = *(const float4*)(am_base + k0 + tx * 4);
            float4 val;
            val.x = -10000.0f + am4.x * -10000.0f;
            val.y = -10000.0f + am4.y * -10000.0f;
            val.z = -10000.0f + am4.z * -10000.0f;
            val.w = -10000.0f + am4.w * -10000.0f;
            #pragma unroll
            for (int i = 0; i < 4; i++)
                *(float4*)&sc[(size_t)(ty * 4 + i) * SS + k0 + tx * 4] = val;
        }
    }

    // ctx = acc / l  -> g_ctx[b,s,h*64+d]
    #pragma unroll
    for (int i = 0; i < 4; i++) {
        const float inv = 1.0f / lrow[i];
        const float2 v0 = unpack2(acc2[i][0]);
        const float2 v1 = unpack2(acc2[i][1]);
        const float4 o = make_float4(v0.x * inv, v0.y * inv, v1.x * inv, v1.y * inv);
        *(float4*)(g_ctx + ((size_t)(b * SS) + q0 + ty * 4 + i) * HH + h * HDD + tx * 4) = o;
    }
}

// ---------------- projection GEMM + residual ----------------
__global__ __launch_bounds__(256) void proj_gemm_kernel(const float* __restrict__ W,
                                                        const float* __restrict__ bias,
                                                        const float* __restrict__ hs,
                                                        float* __restrict__ out) {
    __shared__ float As[16][132];
    __shared__ float Bs[16][128];
    const int tid = threadIdx.x;
    const int ty = tid >> 4, tx = tid & 15;
    const int bm = blockIdx.y, bn = blockIdx.x;
    const float* A  = g_ctx + (size_t)bm * 128 * HH;
    const float* Bw = W + bn * 128;

    ull acc2[8][4];
    #pragma unroll
    for (int i = 0; i < 8; i++)
        #pragma unroll
        for (int j = 0; j < 4; j++) acc2[i][j] = 0ull;

    const int ar = tid >> 1, akb = (tid & 1) * 8;
    const int br = tid >> 5, bc = (tid & 31) * 4;

    float4 a0 = *(const float4*)(A + (size_t)ar * HH + akb);
    float4 a1 = *(const float4*)(A + (size_t)ar * HH + akb + 4);
    float4 b0 = *(const float4*)(Bw + (size_t)br * HH + bc);
    float4 b1 = *(const float4*)(Bw + (size_t)(br + 8) * HH + bc);

    for (int kt = 0; kt < 64; kt++) {
        __syncthreads();
        As[akb+0][ar] = a0.x; As[akb+1][ar] = a0.y; As[akb+2][ar] = a0.z; As[akb+3][ar] = a0.w;
        As[akb+4][ar] = a1.x; As[akb+5][ar] = a1.y; As[akb+6][ar] = a1.z; As[akb+7][ar] = a1.w;
        *(float4*)&Bs[br][bc]     = b0;
        *(float4*)&Bs[br + 8][bc] = b1;
        __syncthreads();
        if (kt < 63) {
            const int k0 = (kt + 1) * 16;
            a0 = *(const float4*)(A + (size_t)ar * HH + k0 + akb);
            a1 = *(const float4*)(A + (size_t)ar * HH + k0 + akb + 4);
            b0 = *(const float4*)(Bw + (size_t)(k0 + br) * HH + bc);
            b1 = *(const float4*)(Bw + (size_t)(k0 + br + 8) * HH + bc);
        }
        #pragma unroll
        for (int kk = 0; kk < 16; kk++) {
            const float4 af0 = *(const float4*)&As[kk][ty * 8];
            const float4 af1 = *(const float4*)&As[kk][ty * 8 + 4];
            const ull* bp = (const ull*)&Bs[kk][tx * 8];
            const ull bb0 = bp[0], bb1 = bp[1], bb2 = bp[2], bb3 = bp[3];
            const float a[8] = {af0.x, af0.y, af0.z, af0.w, af1.x, af1.y, af1.z, af1.w};
            #pragma unroll
            for (int i = 0; i < 8; i++) {
                const ull ai = pack2(a[i]);
                acc2[i][0] = ffma2(ai, bb0, acc2[i][0]);
                acc2[i][1] = ffma2(ai, bb1, acc2[i][1]);
                acc2[i][2] = ffma2(ai, bb2, acc2[i][2]);
                acc2[i][3] = ffma2(ai, bb3, acc2[i][3]);
            }
        }
    }
    #pragma unroll
    for (int i = 0; i < 8; i++) {
        const int m = bm * 128 + ty * 8 + i;
        #pragma unroll
        for (int jj = 0; jj < 2; jj++) {
            const int n = bn * 128 + tx * 8 + jj * 4;
            const float4 b4 = *(const float4*)(bias + n);
            const float4 r4 = *(const float4*)(hs + (size_t)m * HH + n);
            const float2 v0 = unpack2(acc2[i][jj * 2]);
            const float2 v1 = unpack2(acc2[i][jj * 2 + 1]);
            float4 c = make_float4(v0.x + b4.x + r4.x,
                                   v0.y + b4.y + r4.y,
                                   v1.x + b4.z + r4.z,
                                   v1.y + b4.w + r4.w);
            *(float4*)(out + (size_t)m * HH + n) = c;
        }
    }
}

// ---------------- launch ----------------
extern "C" void kernel_launch(void* const* d_in, const int* in_sizes, int n_in,
                              void* d_out, int out_size) {
    const float* hs       = (const float*)d_in[0];
    const float* amask    = (const float*)d_in[1];
    const float* c_attn_w = (const float*)d_in[2];
    const float* c_attn_b = (const float*)d_in[3];
    const float* c_proj_w = (const float*)d_in[4];
    const float* c_proj_b = (const float*)d_in[5];
    const float* ln_g     = (const float*)d_in[6];
    const float* ln_b     = (const float*)d_in[7];
    float* out = (float*)d_out;
    float* scores = (out_size > MM * HH) ? (out + (size_t)MM * HH) : nullptr;

    ln_kernel<<<MM, 256>>>(hs, ln_g, ln_b);
    qkv_gemm_kernel<<<dim3(N3 / 128, MM / 128), 256>>>(c_attn_w, c_attn_b);
    cudaFuncSetAttribute(attn_kernel, cudaFuncAttributeMaxDynamicSharedMemorySize, ATTN_SMEM);
    attn_kernel<<<dim3(32, NHH, BB), 256, ATTN_SMEM>>>(amask, scores);
    proj_gemm_kernel<<<dim3(HH / 128, MM / 128), 256>>>(c_proj_w, c_proj_b, hs, out);
}

// round 5
// speedup vs baseline: 1.4712x; 1.4055x over previous
#include <cuda_runtime.h>
#include <cuda_bf16.h>
#include <cstdint>

#define BB   4
#define SS   2048
#define HH   1024
#define NHH  16
#define HDD  64
#define MM   (BB*SS)      // 8192
#define N3   (3*HH)       // 3072
#define KK   1024
#define STR  40           // smem row stride in bf16 (80B -> conflict-free ldmatrix)

typedef unsigned long long ull;

// ---------------- packed f32x2 helpers (attention kernel) ----------------
__device__ __forceinline__ ull ffma2(ull a, ull b, ull c) {
    ull d;
    asm("fma.rn.f32x2 %0, %1, %2, %3;" : "=l"(d) : "l"(a), "l"(b), "l"(c));
    return d;
}
__device__ __forceinline__ ull fmul2(ull a, ull b) {
    ull d;
    asm("mul.rn.f32x2 %0, %1, %2;" : "=l"(d) : "l"(a), "l"(b));
    return d;
}
__device__ __forceinline__ ull pack2(float x) {
    ull r;
    asm("mov.b64 %0, {%1, %1};" : "=l"(r) : "f"(x));
    return r;
}
__device__ __forceinline__ float2 unpack2(ull v) {
    float2 r;
    asm("mov.b64 {%0, %1}, %2;" : "=f"(r.x), "=f"(r.y) : "l"(v));
    return r;
}

// ---------------- tensor-core helpers (arch-portable mma.sync path) ----------------
__device__ __forceinline__ uint32_t smem_u32(const void* p) {
    uint32_t a;
    asm("{ .reg .u64 t; cvta.to.shared.u64 t, %1; cvt.u32.u64 %0, t; }" : "=r"(a) : "l"(p));
    return a;
}
__device__ __forceinline__ void ldsm4(uint32_t* r, uint32_t addr) {
    asm volatile("ldmatrix.sync.aligned.m8n8.x4.shared.b16 {%0,%1,%2,%3}, [%4];"
        : "=r"(r[0]), "=r"(r[1]), "=r"(r[2]), "=r"(r[3]) : "r"(addr));
}
__device__ __forceinline__ void mma16816(float* c, const uint32_t* a, const uint32_t* b) {
    asm volatile("mma.sync.aligned.m16n8k16.row.col.f32.bf16.bf16.f32 "
        "{%0,%1,%2,%3}, {%4,%5,%6,%7}, {%8,%9}, {%0,%1,%2,%3};"
        : "+f"(c[0]), "+f"(c[1]), "+f"(c[2]), "+f"(c[3])
        : "r"(a[0]), "r"(a[1]), "r"(a[2]), "r"(a[3]), "r"(b[0]), "r"(b[1]));
}

// ---------------- scratch (__device__ globals; no runtime alloc) ----------------
__device__ __align__(128) __nv_bfloat16 g_xh[(size_t)MM * KK];     // LN out hi
__device__ __align__(128) __nv_bfloat16 g_xl[(size_t)MM * KK];     // LN out lo
__device__ __align__(128) __nv_bfloat16 g_wqh[(size_t)N3 * KK];    // qkv W^T hi [3072,1024]
__device__ __align__(128) __nv_bfloat16 g_wql[(size_t)N3 * KK];
__device__ __align__(128) __nv_bfloat16 g_wph[(size_t)HH * KK];    // proj W^T hi [1024,1024]
__device__ __align__(128) __nv_bfloat16 g_wpl[(size_t)HH * KK];
__device__ __align__(128) __nv_bfloat16 g_ch[(size_t)MM * HH];     // ctx hi
__device__ __align__(128) __nv_bfloat16 g_cl[(size_t)MM * HH];     // ctx lo
__device__ float g_q[(size_t)BB * NHH * SS * HDD];                 // [b,h,s,d]
__device__ float g_k[(size_t)BB * NHH * SS * HDD];
__device__ float g_v[(size_t)BB * NHH * SS * HDD];

// ---------------- layernorm + bf16 hi/lo split ----------------
__global__ __launch_bounds__(256) void ln_kernel(const float* __restrict__ hs,
                                                 const float* __restrict__ gamma,
                                                 const float* __restrict__ beta) {
    const int row = blockIdx.x;
    const int tid = threadIdx.x;
    const float4 v = ((const float4*)(hs + (size_t)row * HH))[tid];
    float s  = v.x + v.y + v.z + v.w;
    float s2 = v.x*v.x + v.y*v.y + v.z*v.z + v.w*v.w;
    #pragma unroll
    for (int o = 16; o > 0; o >>= 1) {
        s  += __shfl_xor_sync(0xffffffffu, s,  o);
        s2 += __shfl_xor_sync(0xffffffffu, s2, o);
    }
    __shared__ float red[2][8];
    const int wid = tid >> 5, lane = tid & 31;
    if (lane == 0) { red[0][wid] = s; red[1][wid] = s2; }
    __syncthreads();
    float mean = 0.f, msq = 0.f;
    #pragma unroll
    for (int i = 0; i < 8; i++) { mean += red[0][i]; msq += red[1][i]; }
    mean *= (1.0f / HH);
    msq  *= (1.0f / HH);
    const float rstd = rsqrtf(msq - mean * mean + 1e-5f);
    const float4 g = ((const float4*)gamma)[tid];
    const float4 b = ((const float4*)beta)[tid];
    float o[4];
    o[0] = (v.x - mean) * rstd * g.x + b.x;
    o[1] = (v.y - mean) * rstd * g.y + b.y;
    o[2] = (v.z - mean) * rstd * g.z + b.z;
    o[3] = (v.w - mean) * rstd * g.w + b.w;
    __nv_bfloat16 h[4], l[4];
    #pragma unroll
    for (int i = 0; i < 4; i++) {
        h[i] = __float2bfloat16(o[i]);
        l[i] = __float2bfloat16(o[i] - __bfloat162float(h[i]));
    }
    const size_t off = (size_t)row * HH + tid * 4;
    *(__nv_bfloat162*)(g_xh + off)     = __nv_bfloat162(h[0], h[1]);
    *(__nv_bfloat162*)(g_xh + off + 2) = __nv_bfloat162(h[2], h[3]);
    *(__nv_bfloat162*)(g_xl + off)     = __nv_bfloat162(l[0], l[1]);
    *(__nv_bfloat162*)(g_xl + off + 2) = __nv_bfloat162(l[2], l[3]);
}

// ---------------- weight transpose + split: W[K=1024, N] -> WT_h/WT_l [N, 1024] ----
__global__ __launch_bounds__(256) void wsplit_kernel(const float* __restrict__ W,
                                                     __nv_bfloat16* __restrict__ Th,
                                                     __nv_bfloat16* __restrict__ Tl,
                                                     int N) {
    __shared__ float sm[32][33];
    const int n0 = blockIdx.x * 32, k0 = blockIdx.y * 32;
    const int tx = threadIdx.x & 31, ty = threadIdx.x >> 5;
    #pragma unroll
    for (int i = 0; i < 4; i++) {
        const int k = ty * 4 + i;
        sm[k][tx] = W[(size_t)(k0 + k) * N + n0 + tx];
    }
    __syncthreads();
    #pragma unroll
    for (int i = 0; i < 4; i++) {
        const int n = ty * 4 + i;
        const float v = sm[tx][n];
        const __nv_bfloat16 h = __float2bfloat16(v);
        const __nv_bfloat16 l = __float2bfloat16(v - __bfloat162float(h));
        Th[(size_t)(n0 + n) * KK + k0 + tx] = h;
        Tl[(size_t)(n0 + n) * KK + k0 + tx] = l;
    }
}

// ---------------- split-bf16 mma.sync GEMM: C[128x128] = A[M,K] @ B[N,K]^T ----------
// EPI 0: qkv bias+scatter into g_q/g_k/g_v.  EPI 1: out = acc + bias + resid.
#define MMA_SMEM (8 * 128 * STR * 2)   // 4 operands x 2 buffers x 128 x STR bf16
template<int EPI>
__global__ __launch_bounds__(256) void mma_gemm_kernel(
    const __nv_bfloat16* __restrict__ Ah, const __nv_bfloat16* __restrict__ Al,
    const __nv_bfloat16* __restrict__ Bh, const __nv_bfloat16* __restrict__ Bl,
    const float* __restrict__ bias, const float* __restrict__ resid,
    float* __restrict__ outp)
{
    extern __shared__ __nv_bfloat16 smb[];
    const int tid = threadIdx.x, wid = tid >> 5, lane = tid & 31;
    const int bm = blockIdx.y, bn = blockIdx.x;
    const int wm = wid >> 2, wn = wid & 3;
    const uint32_t sbase = smem_u32(smb);

    const __nv_bfloat16* gA0 = Ah + (size_t)bm * 128 * KK;
    const __nv_bfloat16* gA1 = Al + (size_t)bm * 128 * KK;
    const __nv_bfloat16* gB0 = Bh + (size_t)bn * 128 * KK;
    const __nv_bfloat16* gB1 = Bl + (size_t)bn * 128 * KK;

    float c[4][4][4];
    #pragma unroll
    for (int i = 0; i < 4; i++)
        #pragma unroll
        for (int j = 0; j < 4; j++)
            #pragma unroll
            for (int q = 0; q < 4; q++) c[i][j][q] = 0.f;

    const int lrow = tid >> 2;   // 0..63, second half +64
    const int lseg = tid & 3;

    uint4 pre[4][2];
    auto gload = [&](int k0) {
        #pragma unroll
        for (int op = 0; op < 4; op++) {
            const __nv_bfloat16* src = (op == 0) ? gA0 : (op == 1) ? gA1 : (op == 2) ? gB0 : gB1;
            #pragma unroll
            for (int i = 0; i < 2; i++) {
                const int row = lrow + i * 64;
                pre[op][i] = *(const uint4*)(src + (size_t)row * KK + k0 + lseg * 8);
            }
        }
    };
    auto s2s = [&](int buf) {
        #pragma unroll
        for (int op = 0; op < 4; op++)
            #pragma unroll
            for (int i = 0; i < 2; i++) {
                const int row = lrow + i * 64;
                *(uint4*)(smb + (size_t)(buf * 4 + op) * 128 * STR + row * STR + lseg * 8) = pre[op][i];
            }
    };

    gload(0);
    s2s(0);
    __syncthreads();

    // ldmatrix per-lane addressing
    const int a_r = lane & 15;
    const int a_c = (lane >> 4) * 8;
    const int b_r = ((lane >> 4) << 3) + (lane & 7);
    const int b_c = ((lane >> 3) & 1) * 8;

    const int NCH = KK / 32;  // 32
    for (int ch = 0; ch < NCH; ch++) {
        const int buf = ch & 1;
        if (ch + 1 < NCH) gload((ch + 1) * 32);
        #pragma unroll
        for (int pass = 0; pass < 3; pass++) {
            const int aop = (pass == 2) ? 1 : 0;
            const int bop = (pass == 1) ? 3 : 2;
            const uint32_t abase = sbase + (uint32_t)((buf * 4 + aop) * 128 * STR) * 2;
            const uint32_t bbase = sbase + (uint32_t)((buf * 4 + bop) * 128 * STR) * 2;
            #pragma unroll
            for (int ks = 0; ks < 2; ks++) {
                uint32_t a[4][4], b[2][4];
                #pragma unroll
                for (int mi = 0; mi < 4; mi++)
                    ldsm4(a[mi], abase + (uint32_t)((wm * 64 + mi * 16 + a_r) * STR + ks * 16 + a_c) * 2);
                #pragma unroll
                for (int pj = 0; pj < 2; pj++)
                    ldsm4(b[pj], bbase + (uint32_t)((wn * 32 + pj * 16 + b_r) * STR + ks * 16 + b_c) * 2);
                #pragma unroll
                for (int mi = 0; mi < 4; mi++)
                    #pragma unroll
                    for (int nj = 0; nj < 4; nj++)
                        mma16816(c[mi][nj], a[mi], &b[nj >> 1][(nj & 1) * 2]);
            }
        }
        if (ch + 1 < NCH) s2s(1 - buf);
        __syncthreads();
    }

    // epilogue
    #pragma unroll
    for (int mi = 0; mi < 4; mi++) {
        #pragma unroll
        for (int half = 0; half < 2; half++) {
            const int r = bm * 128 + wm * 64 + mi * 16 + (lane >> 2) + half * 8;
            #pragma unroll
            for (int nj = 0; nj < 4; nj++) {
                const int n = bn * 128 + wn * 32 + nj * 8 + (lane & 3) * 2;
                const float v0 = c[mi][nj][half * 2];
                const float v1 = c[mi][nj][half * 2 + 1];
                const float2 b2 = *(const float2*)(bias + n);
                if (EPI == 0) {
                    const int part = n >> 10, rr = n & 1023;
                    const int hh = rr >> 6, d = rr & 63;
                    float* dst = (part == 0) ? g_q : ((part == 1) ? g_k : g_v);
                    const int bidx = r >> 11, srow = r & 2047;
                    *(float2*)(dst + ((size_t)((bidx * NHH + hh) * SS + srow)) * HDD + d) =
                        make_float2(v0 + b2.x, v1 + b2.y);
                } else {
                    const float2 r2 = *(const float2*)(resid + (size_t)r * HH + n);
                    *(float2*)(outp + (size_t)r * HH + n) =
                        make_float2(v0 + b2.x + r2.x, v1 + b2.y + r2.y);
                }
            }
        }
    }
}

// ---------------- flash attention + raw score emission ----------------
#define ATTN_SMEM (3 * 64 * 68 * 4)
__global__ __launch_bounds__(256) void attn_kernel(const float* __restrict__ amask,
                                                   float* __restrict__ scores_out) {
    extern __shared__ float sm[];
    float (*Qst)[68] = (float (*)[68])sm;                 // [d][q]
    float (*KPs)[68] = (float (*)[68])(sm + 64 * 68);     // K as [d][kc], then P^T
    float (*Vs )[68] = (float (*)[68])(sm + 2 * 64 * 68); // [kc][d]

    const int qt = 31 - blockIdx.x;
    const int hidx = blockIdx.y;
    const int b  = blockIdx.z;
    const int tid = threadIdx.x;
    const int ty = tid >> 4, tx = tid & 15;
    const int q0 = qt * 64;

    const float* Qg = g_q + (size_t)(b * NHH + hidx) * SS * HDD;
    const float* Kg = g_k + (size_t)(b * NHH + hidx) * SS * HDD;
    const float* Vg = g_v + (size_t)(b * NHH + hidx) * SS * HDD;
    float* sc = scores_out ? scores_out + ((size_t)(b * NHH + hidx) * SS + q0) * SS : nullptr;
    const float* am_base = amask + b * SS;

    {
        const int r = tid >> 2;
        const int dbase = (tid & 3) * 16;
        const float4* src = (const float4*)(Qg + (size_t)(q0 + r) * HDD + dbase);
        #pragma unroll
        for (int i = 0; i < 4; i++) {
            const float4 v = src[i];
            Qst[dbase + 4*i + 0][r] = v.x; Qst[dbase + 4*i + 1][r] = v.y;
            Qst[dbase + 4*i + 2][r] = v.z; Qst[dbase + 4*i + 3][r] = v.w;
        }
    }

    ull acc2[4][2];
    float mrow[4], lrow[4];
    #pragma unroll
    for (int i = 0; i < 4; i++) {
        mrow[i] = -1e30f; lrow[i] = 0.f;
        acc2[i][0] = 0ull; acc2[i][1] = 0ull;
    }

    for (int kt = 0; kt <= qt; kt++) {
        const int k0 = kt * 64;
        __syncthreads();
        {
            const int r = tid >> 2;
            const int dbase = (tid & 3) * 16;
            const float4* ks = (const float4*)(Kg + (size_t)(k0 + r) * HDD + dbase);
            const float4* vs = (const float4*)(Vg + (size_t)(k0 + r) * HDD + dbase);
            #pragma unroll
            for (int i = 0; i < 4; i++) {
                const float4 kv = ks[i];
                KPs[dbase + 4*i + 0][r] = kv.x; KPs[dbase + 4*i + 1][r] = kv.y;
                KPs[dbase + 4*i + 2][r] = kv.z; KPs[dbase + 4*i + 3][r] = kv.w;
                *(float4*)&Vs[r][dbase + 4*i] = vs[i];
            }
        }
        __syncthreads();

        ull s2[4][2];
        #pragma unroll
        for (int i = 0; i < 4; i++) { s2[i][0] = 0ull; s2[i][1] = 0ull; }
        #pragma unroll
        for (int kk = 0; kk < 64; kk++) {
            const float4 qf = *(const float4*)&Qst[kk][ty * 4];
            const ull* kp = (const ull*)&KPs[kk][tx * 4];
            const ull kk0 = kp[0], kk1 = kp[1];
            const float qa[4] = {qf.x, qf.y, qf.z, qf.w};
            #pragma unroll
            for (int i = 0; i < 4; i++) {
                const ull qi = pack2(qa[i]);
                s2[i][0] = ffma2(qi, kk0, s2[i][0]);
                s2[i][1] = ffma2(qi, kk1, s2[i][1]);
            }
        }

        float s[4][4];
        #pragma unroll
        for (int i = 0; i < 4; i++) {
            const float2 v0 = unpack2(s2[i][0]);
            const float2 v1 = unpack2(s2[i][1]);
            s[i][0] = v0.x; s[i][1] = v0.y; s[i][2] = v1.x; s[i][3] = v1.y;
        }

        const float4 am4 = *(const float4*)(am_base + k0 + tx * 4);
        const float am[4] = {am4.x, am4.y, am4.z, am4.w};
        const bool diag = (kt == qt);
        #pragma unroll
        for (int i = 0; i < 4; i++) {
            const int qg = q0 + ty * 4 + i;
            #pragma unroll
            for (int j = 0; j < 4; j++) {
                float v = s[i][j] * 0.125f;
                if (diag && (k0 + tx * 4 + j) > qg) v = -10000.0f;
                v += am[j] * -10000.0f;
                s[i][j] = v;
            }
        }
        if (sc) {
            #pragma unroll
            for (int i = 0; i < 4; i++)
                *(float4*)&sc[(size_t)(ty * 4 + i) * SS + k0 + tx * 4] =
                    make_float4(s[i][0], s[i][1], s[i][2], s[i][3]);
        }

        #pragma unroll
        for (int i = 0; i < 4; i++) {
            float tmax = fmaxf(fmaxf(s[i][0], s[i][1]), fmaxf(s[i][2], s[i][3]));
            #pragma unroll
            for (int o = 8; o > 0; o >>= 1)
                tmax = fmaxf(tmax, __shfl_xor_sync(0xffffffffu, tmax, o, 16));
            const float mnew = fmaxf(mrow[i], tmax);
            const float alpha = __expf(mrow[i] - mnew);
            float psum = 0.f;
            #pragma unroll
            for (int j = 0; j < 4; j++) { s[i][j] = __expf(s[i][j] - mnew); psum += s[i][j]; }
            #pragma unroll
            for (int o = 8; o > 0; o >>= 1)
                psum += __shfl_xor_sync(0xffffffffu, psum, o, 16);
            lrow[i] = lrow[i] * alpha + psum;
            mrow[i] = mnew;
            const ull al2 = pack2(alpha);
            acc2[i][0] = fmul2(acc2[i][0], al2);
            acc2[i][1] = fmul2(acc2[i][1], al2);
        }

        __syncthreads();
        #pragma unroll
        for (int i = 0; i < 4; i++)
            #pragma unroll
            for (int j = 0; j < 4; j++) KPs[tx * 4 + j][ty * 4 + i] = s[i][j];  // P^T
        __syncthreads();

        #pragma unroll
        for (int kk = 0; kk < 64; kk++) {
            const float4 pf = *(const float4*)&KPs[kk][ty * 4];
            const ull* vp = (const ull*)&Vs[kk][tx * 4];
            const ull vv0 = vp[0], vv1 = vp[1];
            const float pa[4] = {pf.x, pf.y, pf.z, pf.w};
            #pragma unroll
            for (int i = 0; i < 4; i++) {
                const ull pi = pack2(pa[i]);
                acc2[i][0] = ffma2(pi, vv0, acc2[i][0]);
                acc2[i][1] = ffma2(pi, vv1, acc2[i][1]);
            }
        }
    }

    if (sc) {
        for (int kt = qt + 1; kt < 32; kt++) {
            const int k0 = kt * 64;
            const float4 am4 = *(const float4*)(am_base + k0 + tx * 4);
            float4 val;
            val.x = -10000.0f + am4.x * -10000.0f;
            val.y = -10000.0f + am4.y * -10000.0f;
            val.z = -10000.0f + am4.z * -10000.0f;
            val.w = -10000.0f + am4.w * -10000.0f;
            #pragma unroll
            for (int i = 0; i < 4; i++)
                *(float4*)&sc[(size_t)(ty * 4 + i) * SS + k0 + tx * 4] = val;
        }
    }

    // ctx -> bf16 hi/lo split for proj GEMM
    #pragma unroll
    for (int i = 0; i < 4; i++) {
        const float inv = 1.0f / lrow[i];
        const float2 v0 = unpack2(acc2[i][0]);
        const float2 v1 = unpack2(acc2[i][1]);
        const float o[4] = {v0.x * inv, v0.y * inv, v1.x * inv, v1.y * inv};
        __nv_bfloat16 h[4], l[4];
        #pragma unroll
        for (int j = 0; j < 4; j++) {
            h[j] = __float2bfloat16(o[j]);
            l[j] = __float2bfloat16(o[j] - __bfloat162float(h[j]));
        }
        const size_t off = ((size_t)(b * SS) + q0 + ty * 4 + i) * HH + hidx * HDD + tx * 4;
        *(__nv_bfloat162*)(g_ch + off)     = __nv_bfloat162(h[0], h[1]);
        *(__nv_bfloat162*)(g_ch + off + 2) = __nv_bfloat162(h[2], h[3]);
        *(__nv_bfloat162*)(g_cl + off)     = __nv_bfloat162(l[0], l[1]);
        *(__nv_bfloat162*)(g_cl + off + 2) = __nv_bfloat162(l[2], l[3]);
    }
}

// ---------------- launch ----------------
extern "C" void kernel_launch(void* const* d_in, const int* in_sizes, int n_in,
                              void* d_out, int out_size) {
    const float* hs       = (const float*)d_in[0];
    const float* amask    = (const float*)d_in[1];
    const float* c_attn_w = (const float*)d_in[2];
    const float* c_attn_b = (const float*)d_in[3];
    const float* c_proj_w = (const float*)d_in[4];
    const float* c_proj_b = (const float*)d_in[5];
    const float* ln_g     = (const float*)d_in[6];
    const float* ln_b     = (const float*)d_in[7];
    float* out = (float*)d_out;
    float* scores = (out_size > MM * HH) ? (out + (size_t)MM * HH) : nullptr;

    __nv_bfloat16 *xh, *xl, *wqh, *wql, *wph, *wpl, *ch, *cl;
    cudaGetSymbolAddress((void**)&xh,  g_xh);
    cudaGetSymbolAddress((void**)&xl,  g_xl);
    cudaGetSymbolAddress((void**)&wqh, g_wqh);
    cudaGetSymbolAddress((void**)&wql, g_wql);
    cudaGetSymbolAddress((void**)&wph, g_wph);
    cudaGetSymbolAddress((void**)&wpl, g_wpl);
    cudaGetSymbolAddress((void**)&ch,  g_ch);
    cudaGetSymbolAddress((void**)&cl,  g_cl);

    cudaFuncSetAttribute(mma_gemm_kernel<0>, cudaFuncAttributeMaxDynamicSharedMemorySize, MMA_SMEM);
    cudaFuncSetAttribute(mma_gemm_kernel<1>, cudaFuncAttributeMaxDynamicSharedMemorySize, MMA_SMEM);
    cudaFuncSetAttribute(attn_kernel, cudaFuncAttributeMaxDynamicSharedMemorySize, ATTN_SMEM);

    ln_kernel<<<MM, 256>>>(hs, ln_g, ln_b);
    wsplit_kernel<<<dim3(N3 / 32, KK / 32), 256>>>(c_attn_w, wqh, wql, N3);
    wsplit_kernel<<<dim3(HH / 32, KK / 32), 256>>>(c_proj_w, wph, wpl, HH);
    mma_gemm_kernel<0><<<dim3(N3 / 128, MM / 128), 256, MMA_SMEM>>>(
        xh, xl, wqh, wql, c_attn_b, nullptr, nullptr);
    attn_kernel<<<dim3(32, NHH, BB), 256, ATTN_SMEM>>>(amask, scores);
    mma_gemm_kernel<1><<<dim3(HH / 128, MM / 128), 256, MMA_SMEM>>>(
        ch, cl, wph, wpl, c_proj_b, hs, out);
}